// round 7
// baseline (speedup 1.0000x reference)
#include <cuda_runtime.h>
#include <cuda_fp16.h>

#define DD 128
#define MAXN 40000

// ---------------- device scratch (allocation-free rule) ----------------
__device__ float g_Ah[MAXN * DD];
__device__ float g_Bh[MAXN * DD];
__device__ float g_Dh[MAXN * DD];   // holds hs@Wd + bd + bc  (bc folded in)
__device__ float g_Eh[MAXN * DD];
// interleaved num/den: per node 32 blocks of {num[4], den[4]}
__device__ float g_nd[MAXN * 2 * DD];
// 5 transposed fp16 weights, pre-swizzled (blocked layout below)
__device__ __align__(16) unsigned char g_Wh[5 * 32768];

// ---------------- smem layouts ----------------
// edge: W 32KB | A 32KB | C 32KB (128 x 64 f32, xor-swizzled) -> 98304B, 2 CTAs/SM
#define ESM_W 0
#define ESM_A 32768
#define ESM_C 65536
#define ESM_REQ 98304
// node: W 32KB | A 32KB
#define NSM_W 0
#define NSM_A 32768
#define NSM_REQ 65536

// ---------------- helpers ----------------
static __device__ __forceinline__ unsigned smem_u32(const void* p) {
    unsigned a;
    asm("{ .reg .u64 t; cvta.to.shared.u64 t, %1; cvt.u32.u64 %0, t; }" : "=r"(a) : "l"(p));
    return a;
}
// blocked swizzled layout for a 128-row x 128-halfword-col tile (ldmatrix source)
static __device__ __forceinline__ unsigned bsw(int row, int col) {
    unsigned off = (unsigned)((((row >> 3) + ((col >> 6) << 4)) << 10)
                              + ((row & 7) << 7) + ((col & 63) << 1));
    return off ^ ((off >> 3) & 0x70);
}
// C staging swizzle: row-major stride 64 floats, 8-float blocks XOR'd by row
static __device__ __forceinline__ int cswz(int r, int c) {
    return r * 64 + (c ^ ((r & 7) << 3));
}
static __device__ __forceinline__ void ldsm_x4(unsigned& r0, unsigned& r1,
                                               unsigned& r2, unsigned& r3, unsigned addr) {
    asm volatile("ldmatrix.sync.aligned.m8n8.x4.shared.b16 {%0,%1,%2,%3}, [%4];"
                 : "=r"(r0), "=r"(r1), "=r"(r2), "=r"(r3) : "r"(addr));
}
static __device__ __forceinline__ void mma_fp16(float c[4], unsigned a0, unsigned a1,
                                                unsigned a2, unsigned a3,
                                                unsigned b0, unsigned b1) {
    asm volatile("mma.sync.aligned.m16n8k16.row.col.f32.f16.f16.f32 "
                 "{%0,%1,%2,%3}, {%4,%5,%6,%7}, {%8,%9}, {%0,%1,%2,%3};"
                 : "+f"(c[0]), "+f"(c[1]), "+f"(c[2]), "+f"(c[3])
                 : "r"(a0), "r"(a1), "r"(a2), "r"(a3), "r"(b0), "r"(b1));
}
static __device__ __forceinline__ void red_add_v4(float* p, float4 v) {
    asm volatile("red.global.add.v4.f32 [%0], {%1,%2,%3,%4};"
                 :: "l"(p), "f"(v.x), "f"(v.y), "f"(v.z), "f"(v.w) : "memory");
}

// fp32 tile -> fp16, written straight into swizzled smem. 256 threads.
template<bool SCALE>
static __device__ __forceinline__ void load_convert_A(
        const float* __restrict__ X, const float* __restrict__ norm,
        int row0, int M, unsigned char* A) {
    int t = threadIdx.x;
    #pragma unroll
    for (int it = 0; it < 16; it++) {
        int f = t + it * 256;
        int row = f >> 5;
        int col0 = (f & 31) * 4;
        int gr = row0 + row;
        float4 v = make_float4(0.f, 0.f, 0.f, 0.f);
        if (gr < M) {
            v = __ldg((const float4*)(X + (size_t)gr * DD + col0));
            if (SCALE) {
                float nm = __ldg(norm + gr);
                v.x *= nm; v.y *= nm; v.z *= nm; v.w *= nm;
            }
        }
        unsigned p0, p1;
        asm("cvt.rn.f16x2.f32 %0, %1, %2;" : "=r"(p0) : "f"(v.y), "f"(v.x));
        asm("cvt.rn.f16x2.f32 %0, %1, %2;" : "=r"(p1) : "f"(v.w), "f"(v.z));
        *(uint2*)(A + bsw(row, col0)) = make_uint2(p0, p1);
    }
}

// ---------------- fp16 GEMM, 64-col half: 8 warps, warp = 16 rows x 64 cols ----------------
static __device__ __forceinline__ void gemm_fp16_half(
        const unsigned char* smA, const unsigned char* smW, int half, float acc[8][4]) {
    unsigned aB = smem_u32(smA), wB = smem_u32(smW);
    int tid = threadIdx.x, lane = tid & 31, w = tid >> 5;
    int lr = lane & 7, m = lane >> 3;
    int aRow = w * 16 + (m & 1) * 8 + lr;
    int aCol = (m >> 1) * 8;
    int bRow = half * 64 + (m >> 1) * 8 + lr;
    int bCol = (m & 1) * 8;

    #pragma unroll
    for (int n8 = 0; n8 < 8; n8++)
        #pragma unroll
        for (int q = 0; q < 4; q++) acc[n8][q] = 0.f;

    #pragma unroll
    for (int kk = 0; kk < 8; kk++) {
        int k0 = kk * 16;
        unsigned a0, a1, a2, a3;
        ldsm_x4(a0, a1, a2, a3, aB + bsw(aRow, k0 + aCol));
        #pragma unroll
        for (int nt = 0; nt < 4; nt++) {
            unsigned b0, b1, b2, b3;
            ldsm_x4(b0, b1, b2, b3, wB + bsw(bRow + nt * 16, k0 + bCol));
            mma_fp16(acc[nt * 2],     a0, a1, a2, a3, b0, b1);
            mma_fp16(acc[nt * 2 + 1], a0, a1, a2, a3, b2, b3);
        }
    }
}

// ---------------- prep: transpose/convert/swizzle weights ----------------
__global__ void prep_kernel(const float* __restrict__ Wa, const float* __restrict__ Wb,
                            const float* __restrict__ Wc, const float* __restrict__ Wd,
                            const float* __restrict__ We) {
    int idx = blockIdx.x * blockDim.x + threadIdx.x;
    if (idx < 5 * 16384) {
        int mm = idx >> 14;
        int rem = idx & 16383;
        int n = rem >> 7, k = rem & 127;
        const float* W = (mm == 0) ? Wa : (mm == 1) ? Wb : (mm == 2) ? Wc : (mm == 3) ? Wd : We;
        float v = W[k * DD + n];                 // transpose: Wt[n][k] = W[k][n]
        *(__half*)(g_Wh + mm * 32768 + bsw(n, k)) = __float2half_rn(v);
    }
}

__global__ void zero_kernel(int Nn) {
    int idx = blockIdx.x * blockDim.x + threadIdx.x;   // float4 index
    int total = Nn * (2 * DD / 4);
    if (idx < total)
        ((float4*)g_nd)[idx] = make_float4(0.f, 0.f, 0.f, 0.f);
}

// ---------------- node GEMMs: out_y = (h*norm)@W_y + bias ----------------
__global__ __launch_bounds__(256, 2) void node_mma_kernel(
        const float* __restrict__ h, const float* __restrict__ norm,
        const float* __restrict__ ba, const float* __restrict__ bb,
        const float* __restrict__ bd, const float* __restrict__ be,
        const float* __restrict__ bc, int M) {
    extern __shared__ unsigned char sm[];
    int tid = threadIdx.x;
    int y = blockIdx.y;
    int widx = (y == 0) ? 0 : (y == 1) ? 1 : (y == 2) ? 3 : 4;   // a,b,d,e
    float* out        = (y == 0) ? g_Ah : (y == 1) ? g_Bh : (y == 2) ? g_Dh : g_Eh;
    const float* bias = (y == 0) ? ba   : (y == 1) ? bb   : (y == 2) ? bd   : be;
    const float* bias2 = (y == 2) ? bc : nullptr;     // fold bc into Dh
    int row0 = blockIdx.x * 128;

    {
        const uint4* s = (const uint4*)(g_Wh + widx * 32768);
        uint4* d = (uint4*)(sm + NSM_W);
        #pragma unroll
        for (int i = tid; i < 2048; i += 256) d[i] = __ldg(s + i);
    }
    load_convert_A<true>(h, norm, row0, M, sm + NSM_A);
    __syncthreads();

    int lane = tid & 31, w = tid >> 5;
    int rbase = row0 + w * 16 + (lane >> 2);
    int cp = 2 * (lane & 3);

    #pragma unroll
    for (int half = 0; half < 2; half++) {
        float acc[8][4];
        gemm_fp16_half(sm + NSM_A, sm + NSM_W, half, acc);
        #pragma unroll
        for (int n8 = 0; n8 < 8; n8++) {
            int c = half * 64 + n8 * 8 + cp;
            float2 bv = __ldg((const float2*)(bias + c));
            if (bias2) {
                float2 b2 = __ldg((const float2*)(bias2 + c));
                bv.x += b2.x; bv.y += b2.y;
            }
            if (rbase < M)
                *(float2*)(out + (size_t)rbase * DD + c) =
                    make_float2(acc[n8][0] + bv.x, acc[n8][1] + bv.y);
            if (rbase + 8 < M)
                *(float2*)(out + (size_t)(rbase + 8) * DD + c) =
                    make_float2(acc[n8][2] + bv.x, acc[n8][3] + bv.y);
        }
    }
}

// ---------------- edge kernel: tile per CTA; row-granular epilogue via smem C ----------------
__global__ __launch_bounds__(256, 2) void edge_mma_kernel(
        const float* __restrict__ e,
        const int* __restrict__ src, const int* __restrict__ dst,
        float* __restrict__ out_e, int E) {
    extern __shared__ unsigned char sm[];
    int tid = threadIdx.x;
    int tile = blockIdx.x;

    {   // Wc (index 2)
        const uint4* s = (const uint4*)(g_Wh + 2 * 32768);
        uint4* d = (uint4*)(sm + ESM_W);
        #pragma unroll
        for (int i = tid; i < 2048; i += 256) d[i] = __ldg(s + i);
    }
    load_convert_A<false>(e, nullptr, tile * 128, E, sm + ESM_A);
    __syncthreads();

    int lane = tid & 31, w = tid >> 5;
    float* Cf = (float*)(sm + ESM_C);

    // staging coords (fragment layout)
    int sr0 = w * 16 + (lane >> 2);
    int scp = 2 * (lane & 3);
    // epilogue coords (row-granular: 2 edges per warp instruction)
    int sub = lane >> 4;            // 0/1: which of the two edges
    int j   = lane & 15;            // 16 lanes cover 64 cols as float4

    #pragma unroll
    for (int half = 0; half < 2; half++) {
        float acc[8][4];
        gemm_fp16_half(sm + ESM_A, sm + ESM_W, half, acc);

        // stage this warp's 16 rows x 64 cols into warp-private C region
        __syncwarp();
        #pragma unroll
        for (int n8 = 0; n8 < 8; n8++) {
            int cl = n8 * 8 + scp;
            *(float2*)(Cf + cswz(sr0, cl))     = make_float2(acc[n8][0], acc[n8][1]);
            *(float2*)(Cf + cswz(sr0 + 8, cl)) = make_float2(acc[n8][2], acc[n8][3]);
        }
        __syncwarp();

        // epilogue: per iteration, 2 edges x 16 lanes x float4 (contiguous 256B rows)
        #pragma unroll
        for (int k = 0; k < 8; k++) {
            int lr = w * 16 + 2 * k + sub;
            int er = tile * 128 + lr;
            if (er < E) {
                int s = __ldg(src + er);
                int d = __ldg(dst + er);
                int c = half * 64 + 4 * j;
                float4 cx = *(const float4*)(Cf + cswz(lr, 4 * j));
                float4 dh = __ldg((const float4*)(g_Dh + (size_t)s * DD + c));  // has bc+bd
                float4 eh = __ldg((const float4*)(g_Eh + (size_t)d * DD + c));
                float4 x;
                x.x = cx.x + dh.x + eh.x;
                x.y = cx.y + dh.y + eh.y;
                x.z = cx.z + dh.z + eh.z;
                x.w = cx.w + dh.w + eh.w;
                *(float4*)(out_e + (size_t)er * DD + c) = x;
                float4 bh = __ldg((const float4*)(g_Bh + (size_t)s * DD + c));
                float4 sg;
                sg.x = __fdividef(1.f, 1.f + __expf(-x.x));
                sg.y = __fdividef(1.f, 1.f + __expf(-x.y));
                sg.z = __fdividef(1.f, 1.f + __expf(-x.z));
                sg.w = __fdividef(1.f, 1.f + __expf(-x.w));
                float4 nm4 = make_float4(sg.x * bh.x, sg.y * bh.y, sg.z * bh.z, sg.w * bh.w);
                int jj = half * 16 + j;
                float* ndp = g_nd + (size_t)d * (2 * DD) + 8 * jj;
                red_add_v4(ndp, nm4);
                red_add_v4(ndp + 4, sg);
            }
        }
        __syncwarp();   // C reuse across halves is warp-local
    }
}

// ---------------- finalize (deg>0 <=> den>0, sigmoids strictly positive) ----------------
__global__ void finalize_kernel(const float* __restrict__ h,
                                const float* __restrict__ norm,
                                float* __restrict__ out_h, int Nn) {
    int idx = blockIdx.x * blockDim.x + threadIdx.x;   // float4-block index
    int total = Nn * (DD / 4);
    if (idx >= total) return;
    int node = idx >> 5;
    int jj = idx & 31;
    float nm = __ldg(norm + node);
    const float* ndp = g_nd + (size_t)node * (2 * DD) + 8 * jj;
    float4 nu = *(const float4*)(ndp);
    float4 de = *(const float4*)(ndp + 4);
    float4 r;
    if (de.x > 0.f) {
        float4 a = ((const float4*)g_Ah)[idx];
        r.x = (a.x + nu.x / (de.x + 1e-6f)) * nm;
        r.y = (a.y + nu.y / (de.y + 1e-6f)) * nm;
        r.z = (a.z + nu.z / (de.z + 1e-6f)) * nm;
        r.w = (a.w + nu.w / (de.w + 1e-6f)) * nm;
    } else {
        float4 hh = *(const float4*)(h + (size_t)idx * 4);
        float sc = nm * nm;
        r = make_float4(hh.x * sc, hh.y * sc, hh.z * sc, hh.w * sc);
    }
    ((float4*)out_h)[idx] = r;
}

// ---------------- launch ----------------
extern "C" void kernel_launch(void* const* d_in, const int* in_sizes, int n_in,
                              void* d_out, int out_size) {
    const float* h    = (const float*)d_in[0];
    const float* e    = (const float*)d_in[1];
    const float* norm = (const float*)d_in[2];
    const int*   src  = (const int*)d_in[3];
    const int*   dst  = (const int*)d_in[4];
    const float* Wa = (const float*)d_in[5],  *ba = (const float*)d_in[6];
    const float* Wb = (const float*)d_in[7],  *bb = (const float*)d_in[8];
    const float* Wc = (const float*)d_in[9],  *bc = (const float*)d_in[10];
    const float* Wd = (const float*)d_in[11], *bd = (const float*)d_in[12];
    const float* We = (const float*)d_in[13], *be = (const float*)d_in[14];

    int Nn = in_sizes[0] / DD;   // 40000
    int Ee = in_sizes[3];        // 600000

    float* out_h = (float*)d_out;
    float* out_e = out_h + (size_t)Nn * DD;

    cudaFuncSetAttribute(node_mma_kernel, cudaFuncAttributeMaxDynamicSharedMemorySize, NSM_REQ);
    cudaFuncSetAttribute(edge_mma_kernel, cudaFuncAttributeMaxDynamicSharedMemorySize, ESM_REQ);

    // launch order: edge kernel is the 4th launch (ncu captures #4)
    prep_kernel<<<(5 * 16384 + 255) / 256, 256>>>(Wa, Wb, Wc, Wd, We);

    zero_kernel<<<(Nn * (2 * DD / 4) + 255) / 256, 256>>>(Nn);

    dim3 ngrid((Nn + 127) / 128, 4);
    node_mma_kernel<<<ngrid, 256, NSM_REQ>>>(h, norm, ba, bb, bd, be, bc, Nn);

    edge_mma_kernel<<<(Ee + 127) / 128, 256, ESM_REQ>>>(e, src, dst, out_e, Ee);

    finalize_kernel<<<(Nn * (DD / 4) + 255) / 256, 256>>>(h, norm, out_h, Nn);
}

// round 8
// speedup vs baseline: 1.1060x; 1.1060x over previous
#include <cuda_runtime.h>
#include <cuda_fp16.h>

#define DD 128
#define MAXN 40000

// ---------------- device scratch (allocation-free rule) ----------------
__device__ float g_Ah[MAXN * DD];
// interleaved src-side table: per node 32 blocks of {Dh[4] (incl bc+bd), Bh[4] (incl bb)}
__device__ float g_DB[MAXN * 2 * DD];
__device__ float g_Eh[MAXN * DD];   // incl be
// interleaved num/den: per node 32 blocks of {num[4], den[4]}
__device__ float g_nd[MAXN * 2 * DD];
// 5 transposed fp16 weights, pre-swizzled (blocked layout below)
__device__ __align__(16) unsigned char g_Wh[5 * 32768];

// ---------------- smem layouts ----------------
// edge: W 32KB | A 32KB | C 32KB | idx 1KB -> 99328B, 2 CTAs/SM
#define ESM_W 0
#define ESM_A 32768
#define ESM_C 65536
#define ESM_I 98304
#define ESM_REQ 99328
// node: W 32KB | A 32KB
#define NSM_W 0
#define NSM_A 32768
#define NSM_REQ 65536

// ---------------- helpers ----------------
static __device__ __forceinline__ unsigned smem_u32(const void* p) {
    unsigned a;
    asm("{ .reg .u64 t; cvta.to.shared.u64 t, %1; cvt.u32.u64 %0, t; }" : "=r"(a) : "l"(p));
    return a;
}
// blocked swizzled layout for a 128-row x 128-halfword-col tile (ldmatrix source)
static __device__ __forceinline__ unsigned bsw(int row, int col) {
    unsigned off = (unsigned)((((row >> 3) + ((col >> 6) << 4)) << 10)
                              + ((row & 7) << 7) + ((col & 63) << 1));
    return off ^ ((off >> 3) & 0x70);
}
// C staging swizzle: row-major stride 64 floats, 8-float blocks XOR'd by row
static __device__ __forceinline__ int cswz(int r, int c) {
    return r * 64 + (c ^ ((r & 7) << 3));
}
static __device__ __forceinline__ void ldsm_x4(unsigned& r0, unsigned& r1,
                                               unsigned& r2, unsigned& r3, unsigned addr) {
    asm volatile("ldmatrix.sync.aligned.m8n8.x4.shared.b16 {%0,%1,%2,%3}, [%4];"
                 : "=r"(r0), "=r"(r1), "=r"(r2), "=r"(r3) : "r"(addr));
}
static __device__ __forceinline__ void mma_fp16(float c[4], unsigned a0, unsigned a1,
                                                unsigned a2, unsigned a3,
                                                unsigned b0, unsigned b1) {
    asm volatile("mma.sync.aligned.m16n8k16.row.col.f32.f16.f16.f32 "
                 "{%0,%1,%2,%3}, {%4,%5,%6,%7}, {%8,%9}, {%0,%1,%2,%3};"
                 : "+f"(c[0]), "+f"(c[1]), "+f"(c[2]), "+f"(c[3])
                 : "r"(a0), "r"(a1), "r"(a2), "r"(a3), "r"(b0), "r"(b1));
}
static __device__ __forceinline__ void red_add_v4(float* p, float4 v) {
    asm volatile("red.global.add.v4.f32 [%0], {%1,%2,%3,%4};"
                 :: "l"(p), "f"(v.x), "f"(v.y), "f"(v.z), "f"(v.w) : "memory");
}

// fp32 tile -> fp16, written straight into swizzled smem. 256 threads.
template<bool SCALE, bool STREAM>
static __device__ __forceinline__ void load_convert_A(
        const float* __restrict__ X, const float* __restrict__ norm,
        int row0, int M, unsigned char* A) {
    int t = threadIdx.x;
    #pragma unroll
    for (int it = 0; it < 16; it++) {
        int f = t + it * 256;
        int row = f >> 5;
        int col0 = (f & 31) * 4;
        int gr = row0 + row;
        float4 v = make_float4(0.f, 0.f, 0.f, 0.f);
        if (gr < M) {
            const float4* p = (const float4*)(X + (size_t)gr * DD + col0);
            v = STREAM ? __ldcs(p) : __ldg(p);
            if (SCALE) {
                float nm = __ldg(norm + gr);
                v.x *= nm; v.y *= nm; v.z *= nm; v.w *= nm;
            }
        }
        unsigned p0, p1;
        asm("cvt.rn.f16x2.f32 %0, %1, %2;" : "=r"(p0) : "f"(v.y), "f"(v.x));
        asm("cvt.rn.f16x2.f32 %0, %1, %2;" : "=r"(p1) : "f"(v.w), "f"(v.z));
        *(uint2*)(A + bsw(row, col0)) = make_uint2(p0, p1);
    }
}

// ---------------- fp16 GEMM, 64-col half: 8 warps, warp = 16 rows x 64 cols ----------------
static __device__ __forceinline__ void gemm_fp16_half(
        const unsigned char* smA, const unsigned char* smW, int half, float acc[8][4]) {
    unsigned aB = smem_u32(smA), wB = smem_u32(smW);
    int tid = threadIdx.x, lane = tid & 31, w = tid >> 5;
    int lr = lane & 7, m = lane >> 3;
    int aRow = w * 16 + (m & 1) * 8 + lr;
    int aCol = (m >> 1) * 8;
    int bRow = half * 64 + (m >> 1) * 8 + lr;
    int bCol = (m & 1) * 8;

    #pragma unroll
    for (int n8 = 0; n8 < 8; n8++)
        #pragma unroll
        for (int q = 0; q < 4; q++) acc[n8][q] = 0.f;

    #pragma unroll
    for (int kk = 0; kk < 8; kk++) {
        int k0 = kk * 16;
        unsigned a0, a1, a2, a3;
        ldsm_x4(a0, a1, a2, a3, aB + bsw(aRow, k0 + aCol));
        #pragma unroll
        for (int nt = 0; nt < 4; nt++) {
            unsigned b0, b1, b2, b3;
            ldsm_x4(b0, b1, b2, b3, wB + bsw(bRow + nt * 16, k0 + bCol));
            mma_fp16(acc[nt * 2],     a0, a1, a2, a3, b0, b1);
            mma_fp16(acc[nt * 2 + 1], a0, a1, a2, a3, b2, b3);
        }
    }
}

// ---------------- prep: transpose/convert/swizzle weights ----------------
__global__ void prep_kernel(const float* __restrict__ Wa, const float* __restrict__ Wb,
                            const float* __restrict__ Wc, const float* __restrict__ Wd,
                            const float* __restrict__ We) {
    int idx = blockIdx.x * blockDim.x + threadIdx.x;
    if (idx < 5 * 16384) {
        int mm = idx >> 14;
        int rem = idx & 16383;
        int n = rem >> 7, k = rem & 127;
        const float* W = (mm == 0) ? Wa : (mm == 1) ? Wb : (mm == 2) ? Wc : (mm == 3) ? Wd : We;
        float v = W[k * DD + n];                 // transpose: Wt[n][k] = W[k][n]
        *(__half*)(g_Wh + mm * 32768 + bsw(n, k)) = __float2half_rn(v);
    }
}

__global__ void zero_kernel(int Nn) {
    int idx = blockIdx.x * blockDim.x + threadIdx.x;   // float4 index
    int total = Nn * (2 * DD / 4);
    if (idx < total)
        ((float4*)g_nd)[idx] = make_float4(0.f, 0.f, 0.f, 0.f);
}

// ---------------- node GEMMs ----------------
// y: 0 -> Ah (ba, linear), 1 -> Bh (bb, g_DB offset +4), 2 -> Dh (bd+bc, g_DB offset 0),
//    3 -> Eh (be, linear)
__global__ __launch_bounds__(256, 2) void node_mma_kernel(
        const float* __restrict__ h, const float* __restrict__ norm,
        const float* __restrict__ ba, const float* __restrict__ bb,
        const float* __restrict__ bd, const float* __restrict__ be,
        const float* __restrict__ bc, int M) {
    extern __shared__ unsigned char sm[];
    int tid = threadIdx.x;
    int y = blockIdx.y;
    int widx = (y == 0) ? 0 : (y == 1) ? 1 : (y == 2) ? 3 : 4;   // a,b,d,e
    const float* bias = (y == 0) ? ba   : (y == 1) ? bb   : (y == 2) ? bd   : be;
    const float* bias2 = (y == 2) ? bc : nullptr;     // fold bc into Dh
    int row0 = blockIdx.x * 128;

    {
        const uint4* s = (const uint4*)(g_Wh + widx * 32768);
        uint4* d = (uint4*)(sm + NSM_W);
        #pragma unroll
        for (int i = tid; i < 2048; i += 256) d[i] = __ldg(s + i);
    }
    load_convert_A<true, false>(h, norm, row0, M, sm + NSM_A);
    __syncthreads();

    int lane = tid & 31, w = tid >> 5;
    int rbase = row0 + w * 16 + (lane >> 2);
    int cp = 2 * (lane & 3);

    #pragma unroll
    for (int half = 0; half < 2; half++) {
        float acc[8][4];
        gemm_fp16_half(sm + NSM_A, sm + NSM_W, half, acc);
        #pragma unroll
        for (int n8 = 0; n8 < 8; n8++) {
            int c = half * 64 + n8 * 8 + cp;
            float2 bv = __ldg((const float2*)(bias + c));
            if (bias2) {
                float2 b2 = __ldg((const float2*)(bias2 + c));
                bv.x += b2.x; bv.y += b2.y;
            }
            #pragma unroll
            for (int rr = 0; rr < 2; rr++) {
                int r = rbase + rr * 8;
                if (r < M) {
                    float2 v = make_float2(acc[n8][rr * 2] + bv.x, acc[n8][rr * 2 + 1] + bv.y);
                    if (y == 0)
                        *(float2*)(g_Ah + (size_t)r * DD + c) = v;
                    else if (y == 3)
                        *(float2*)(g_Eh + (size_t)r * DD + c) = v;
                    else {
                        size_t base = (size_t)r * (2 * DD) + 8 * (c >> 2) + (c & 3)
                                    + (y == 1 ? 4 : 0);
                        *(float2*)(g_DB + base) = v;
                    }
                }
            }
        }
    }
}

// ---------------- edge kernel: tile per CTA; pipelined row-granular epilogue ----------------
__global__ __launch_bounds__(256, 2) void edge_mma_kernel(
        const float* __restrict__ e,
        const int* __restrict__ src, const int* __restrict__ dst,
        float* __restrict__ out_e, int E) {
    extern __shared__ unsigned char sm[];
    int tid = threadIdx.x;
    int tile = blockIdx.x;

    {   // Wc (index 2)
        const uint4* s = (const uint4*)(g_Wh + 2 * 32768);
        uint4* d = (uint4*)(sm + ESM_W);
        #pragma unroll
        for (int i = tid; i < 2048; i += 256) d[i] = __ldg(s + i);
    }
    // stage src/dst pairs for the tile
    if (tid < 128) {
        int er = tile * 128 + tid;
        int2 sd = (er < E) ? make_int2(__ldg(src + er), __ldg(dst + er))
                           : make_int2(0, 0);
        ((int2*)(sm + ESM_I))[tid] = sd;
    }
    load_convert_A<false, true>(e, nullptr, tile * 128, E, sm + ESM_A);
    __syncthreads();

    int lane = tid & 31, w = tid >> 5;
    float* Cf = (float*)(sm + ESM_C);
    const int2* sidx = (const int2*)(sm + ESM_I);

    // staging coords (fragment layout)
    int sr0 = w * 16 + (lane >> 2);
    int scp = 2 * (lane & 3);
    // epilogue coords (row-granular: 2 edges per warp instruction)
    int sub = lane >> 4;            // 0/1: which of the two edges
    int j   = lane & 15;            // 16 lanes cover 64 cols as float4

    #pragma unroll
    for (int half = 0; half < 2; half++) {
        float acc[8][4];
        gemm_fp16_half(sm + ESM_A, sm + ESM_W, half, acc);

        // stage this warp's 16 rows x 64 cols into warp-private C region
        __syncwarp();
        #pragma unroll
        for (int n8 = 0; n8 < 8; n8++) {
            int cl = n8 * 8 + scp;
            *(float2*)(Cf + cswz(sr0, cl))     = make_float2(acc[n8][0], acc[n8][1]);
            *(float2*)(Cf + cswz(sr0 + 8, cl)) = make_float2(acc[n8][2], acc[n8][3]);
        }
        __syncwarp();

        int jj = half * 16 + j;
        int cc = half * 64 + 4 * j;

        // software-pipelined epilogue: prefetch gathers one iteration ahead
        int2 sd = sidx[w * 16 + sub];
        float4 pd = __ldg((const float4*)(g_DB + (size_t)sd.x * (2 * DD) + 8 * jj));
        float4 pb = __ldg((const float4*)(g_DB + (size_t)sd.x * (2 * DD) + 8 * jj + 4));
        float4 pe = __ldg((const float4*)(g_Eh + (size_t)sd.y * DD + cc));

        #pragma unroll
        for (int k = 0; k < 8; k++) {
            int lr = w * 16 + 2 * k + sub;
            int er = tile * 128 + lr;
            float4 cd = pd, cb = pb, ce = pe;
            int dcur = sd.y;
            if (k < 7) {
                sd = sidx[lr + 2];
                pd = __ldg((const float4*)(g_DB + (size_t)sd.x * (2 * DD) + 8 * jj));
                pb = __ldg((const float4*)(g_DB + (size_t)sd.x * (2 * DD) + 8 * jj + 4));
                pe = __ldg((const float4*)(g_Eh + (size_t)sd.y * DD + cc));
            }
            if (er < E) {
                float4 cx = *(const float4*)(Cf + cswz(lr, 4 * j));
                float4 x;
                x.x = cx.x + cd.x + ce.x;      // cd = Dh + bd + bc
                x.y = cx.y + cd.y + ce.y;
                x.z = cx.z + cd.z + ce.z;
                x.w = cx.w + cd.w + ce.w;
                __stcs((float4*)(out_e + (size_t)er * DD + cc), x);
                float4 sg;
                sg.x = __fdividef(1.f, 1.f + __expf(-x.x));
                sg.y = __fdividef(1.f, 1.f + __expf(-x.y));
                sg.z = __fdividef(1.f, 1.f + __expf(-x.z));
                sg.w = __fdividef(1.f, 1.f + __expf(-x.w));
                float4 nm4 = make_float4(sg.x * cb.x, sg.y * cb.y, sg.z * cb.z, sg.w * cb.w);
                float* ndp = g_nd + (size_t)dcur * (2 * DD) + 8 * jj;
                red_add_v4(ndp, nm4);
                red_add_v4(ndp + 4, sg);
            }
        }
        __syncwarp();   // C reuse across halves is warp-local
    }
}

// ---------------- finalize (deg>0 <=> den>0, sigmoids strictly positive) ----------------
__global__ void finalize_kernel(const float* __restrict__ h,
                                const float* __restrict__ norm,
                                float* __restrict__ out_h, int Nn) {
    int idx = blockIdx.x * blockDim.x + threadIdx.x;   // float4-block index
    int total = Nn * (DD / 4);
    if (idx >= total) return;
    int node = idx >> 5;
    int jj = idx & 31;
    float nm = __ldg(norm + node);
    const float* ndp = g_nd + (size_t)node * (2 * DD) + 8 * jj;
    float4 nu = *(const float4*)(ndp);
    float4 de = *(const float4*)(ndp + 4);
    float4 r;
    if (de.x > 0.f) {
        float4 a = ((const float4*)g_Ah)[idx];
        r.x = (a.x + nu.x / (de.x + 1e-6f)) * nm;
        r.y = (a.y + nu.y / (de.y + 1e-6f)) * nm;
        r.z = (a.z + nu.z / (de.z + 1e-6f)) * nm;
        r.w = (a.w + nu.w / (de.w + 1e-6f)) * nm;
    } else {
        float4 hh = *(const float4*)(h + (size_t)idx * 4);
        float sc = nm * nm;
        r = make_float4(hh.x * sc, hh.y * sc, hh.z * sc, hh.w * sc);
    }
    ((float4*)out_h)[idx] = r;
}

// ---------------- launch ----------------
extern "C" void kernel_launch(void* const* d_in, const int* in_sizes, int n_in,
                              void* d_out, int out_size) {
    const float* h    = (const float*)d_in[0];
    const float* e    = (const float*)d_in[1];
    const float* norm = (const float*)d_in[2];
    const int*   src  = (const int*)d_in[3];
    const int*   dst  = (const int*)d_in[4];
    const float* Wa = (const float*)d_in[5],  *ba = (const float*)d_in[6];
    const float* Wb = (const float*)d_in[7],  *bb = (const float*)d_in[8];
    const float* Wc = (const float*)d_in[9],  *bc = (const float*)d_in[10];
    const float* Wd = (const float*)d_in[11], *bd = (const float*)d_in[12];
    const float* We = (const float*)d_in[13], *be = (const float*)d_in[14];

    int Nn = in_sizes[0] / DD;   // 40000
    int Ee = in_sizes[3];        // 600000

    float* out_h = (float*)d_out;
    float* out_e = out_h + (size_t)Nn * DD;

    cudaFuncSetAttribute(node_mma_kernel, cudaFuncAttributeMaxDynamicSharedMemorySize, NSM_REQ);
    cudaFuncSetAttribute(edge_mma_kernel, cudaFuncAttributeMaxDynamicSharedMemorySize, ESM_REQ);

    // launch order: edge kernel is the 4th launch (ncu captures #4)
    prep_kernel<<<(5 * 16384 + 255) / 256, 256>>>(Wa, Wb, Wc, Wd, We);

    zero_kernel<<<(Nn * (2 * DD / 4) + 255) / 256, 256>>>(Nn);

    dim3 ngrid((Nn + 127) / 128, 4);
    node_mma_kernel<<<ngrid, 256, NSM_REQ>>>(h, norm, ba, bb, bd, be, bc, Nn);

    edge_mma_kernel<<<(Ee + 127) / 128, 256, ESM_REQ>>>(e, src, dst, out_e, Ee);

    finalize_kernel<<<(Nn * (DD / 4) + 255) / 256, 256>>>(h, norm, out_h, Nn);
}

// round 9
// speedup vs baseline: 1.2262x; 1.1087x over previous
#include <cuda_runtime.h>
#include <cuda_fp16.h>

#define DD 128
#define MAXN 40000

// ---------------- device scratch (allocation-free rule) ----------------
__device__ float g_Ah[MAXN * DD];
// fp16 interleaved src-side table: per node 32 blocks of {Dh[4] (incl bc+bd), Bh[4] (incl bb)}
__device__ __align__(16) __half g_DB[MAXN * 2 * DD];
__device__ __align__(16) __half g_Eh16[MAXN * DD];   // incl be
// interleaved num/den: per node 32 blocks of {num[4], den[4]}
__device__ float g_nd[MAXN * 2 * DD];
// 5 transposed fp16 weights, pre-swizzled (blocked layout below)
__device__ __align__(16) unsigned char g_Wh[5 * 32768];

// ---------------- smem layouts ----------------
// edge: W 32KB | A 32KB | C 32KB | idx 1KB -> 99328B, 2 CTAs/SM
#define ESM_W 0
#define ESM_A 32768
#define ESM_C 65536
#define ESM_I 98304
#define ESM_REQ 99328
// node: W 32KB | A 32KB
#define NSM_W 0
#define NSM_A 32768
#define NSM_REQ 65536

// ---------------- helpers ----------------
static __device__ __forceinline__ unsigned smem_u32(const void* p) {
    unsigned a;
    asm("{ .reg .u64 t; cvta.to.shared.u64 t, %1; cvt.u32.u64 %0, t; }" : "=r"(a) : "l"(p));
    return a;
}
// blocked swizzled layout for a 128-row x 128-halfword-col tile (ldmatrix source)
static __device__ __forceinline__ unsigned bsw(int row, int col) {
    unsigned off = (unsigned)((((row >> 3) + ((col >> 6) << 4)) << 10)
                              + ((row & 7) << 7) + ((col & 63) << 1));
    return off ^ ((off >> 3) & 0x70);
}
// C staging swizzle: row-major stride 64 floats, 8-float blocks XOR'd by row
static __device__ __forceinline__ int cswz(int r, int c) {
    return r * 64 + (c ^ ((r & 7) << 3));
}
static __device__ __forceinline__ void ldsm_x4(unsigned& r0, unsigned& r1,
                                               unsigned& r2, unsigned& r3, unsigned addr) {
    asm volatile("ldmatrix.sync.aligned.m8n8.x4.shared.b16 {%0,%1,%2,%3}, [%4];"
                 : "=r"(r0), "=r"(r1), "=r"(r2), "=r"(r3) : "r"(addr));
}
static __device__ __forceinline__ void mma_fp16(float c[4], unsigned a0, unsigned a1,
                                                unsigned a2, unsigned a3,
                                                unsigned b0, unsigned b1) {
    asm volatile("mma.sync.aligned.m16n8k16.row.col.f32.f16.f16.f32 "
                 "{%0,%1,%2,%3}, {%4,%5,%6,%7}, {%8,%9}, {%0,%1,%2,%3};"
                 : "+f"(c[0]), "+f"(c[1]), "+f"(c[2]), "+f"(c[3])
                 : "r"(a0), "r"(a1), "r"(a2), "r"(a3), "r"(b0), "r"(b1));
}
static __device__ __forceinline__ void red_add_v4(float* p, float4 v) {
    asm volatile("red.global.add.v4.f32 [%0], {%1,%2,%3,%4};"
                 :: "l"(p), "f"(v.x), "f"(v.y), "f"(v.z), "f"(v.w) : "memory");
}
static __device__ __forceinline__ float2 h2f(unsigned u) {
    return __half22float2(*(__half2*)&u);
}

// fp32 tile -> fp16, written straight into swizzled smem. 256 threads.
template<bool SCALE, bool STREAM>
static __device__ __forceinline__ void load_convert_A(
        const float* __restrict__ X, const float* __restrict__ norm,
        int row0, int M, unsigned char* A) {
    int t = threadIdx.x;
    #pragma unroll
    for (int it = 0; it < 16; it++) {
        int f = t + it * 256;
        int row = f >> 5;
        int col0 = (f & 31) * 4;
        int gr = row0 + row;
        float4 v = make_float4(0.f, 0.f, 0.f, 0.f);
        if (gr < M) {
            const float4* p = (const float4*)(X + (size_t)gr * DD + col0);
            v = STREAM ? __ldcs(p) : __ldg(p);
            if (SCALE) {
                float nm = __ldg(norm + gr);
                v.x *= nm; v.y *= nm; v.z *= nm; v.w *= nm;
            }
        }
        unsigned p0, p1;
        asm("cvt.rn.f16x2.f32 %0, %1, %2;" : "=r"(p0) : "f"(v.y), "f"(v.x));
        asm("cvt.rn.f16x2.f32 %0, %1, %2;" : "=r"(p1) : "f"(v.w), "f"(v.z));
        *(uint2*)(A + bsw(row, col0)) = make_uint2(p0, p1);
    }
}

// ---------------- fp16 GEMM, 64-col half: 8 warps, warp = 16 rows x 64 cols ----------------
static __device__ __forceinline__ void gemm_fp16_half(
        const unsigned char* smA, const unsigned char* smW, int half, float acc[8][4]) {
    unsigned aB = smem_u32(smA), wB = smem_u32(smW);
    int tid = threadIdx.x, lane = tid & 31, w = tid >> 5;
    int lr = lane & 7, m = lane >> 3;
    int aRow = w * 16 + (m & 1) * 8 + lr;
    int aCol = (m >> 1) * 8;
    int bRow = half * 64 + (m >> 1) * 8 + lr;
    int bCol = (m & 1) * 8;

    #pragma unroll
    for (int n8 = 0; n8 < 8; n8++)
        #pragma unroll
        for (int q = 0; q < 4; q++) acc[n8][q] = 0.f;

    #pragma unroll
    for (int kk = 0; kk < 8; kk++) {
        int k0 = kk * 16;
        unsigned a0, a1, a2, a3;
        ldsm_x4(a0, a1, a2, a3, aB + bsw(aRow, k0 + aCol));
        #pragma unroll
        for (int nt = 0; nt < 4; nt++) {
            unsigned b0, b1, b2, b3;
            ldsm_x4(b0, b1, b2, b3, wB + bsw(bRow + nt * 16, k0 + bCol));
            mma_fp16(acc[nt * 2],     a0, a1, a2, a3, b0, b1);
            mma_fp16(acc[nt * 2 + 1], a0, a1, a2, a3, b2, b3);
        }
    }
}

// ---------------- prep: transpose/convert/swizzle weights ----------------
__global__ void prep_kernel(const float* __restrict__ Wa, const float* __restrict__ Wb,
                            const float* __restrict__ Wc, const float* __restrict__ Wd,
                            const float* __restrict__ We) {
    int idx = blockIdx.x * blockDim.x + threadIdx.x;
    if (idx < 5 * 16384) {
        int mm = idx >> 14;
        int rem = idx & 16383;
        int n = rem >> 7, k = rem & 127;
        const float* W = (mm == 0) ? Wa : (mm == 1) ? Wb : (mm == 2) ? Wc : (mm == 3) ? Wd : We;
        float v = W[k * DD + n];                 // transpose: Wt[n][k] = W[k][n]
        *(__half*)(g_Wh + mm * 32768 + bsw(n, k)) = __float2half_rn(v);
    }
}

__global__ void zero_kernel(int Nn) {
    int idx = blockIdx.x * blockDim.x + threadIdx.x;   // float4 index
    int total = Nn * (2 * DD / 4);
    if (idx < total)
        ((float4*)g_nd)[idx] = make_float4(0.f, 0.f, 0.f, 0.f);
}

// ---------------- node GEMMs ----------------
// y: 0 -> Ah (ba, fp32 linear), 1 -> Bh (bb, g_DB half, +4), 2 -> Dh (bd+bc, g_DB half, +0),
//    3 -> Eh (be, g_Eh16 half linear)
__global__ __launch_bounds__(256, 2) void node_mma_kernel(
        const float* __restrict__ h, const float* __restrict__ norm,
        const float* __restrict__ ba, const float* __restrict__ bb,
        const float* __restrict__ bd, const float* __restrict__ be,
        const float* __restrict__ bc, int M) {
    extern __shared__ unsigned char sm[];
    int tid = threadIdx.x;
    int y = blockIdx.y;
    int widx = (y == 0) ? 0 : (y == 1) ? 1 : (y == 2) ? 3 : 4;   // a,b,d,e
    const float* bias = (y == 0) ? ba   : (y == 1) ? bb   : (y == 2) ? bd   : be;
    const float* bias2 = (y == 2) ? bc : nullptr;     // fold bc into Dh
    int row0 = blockIdx.x * 128;

    {
        const uint4* s = (const uint4*)(g_Wh + widx * 32768);
        uint4* d = (uint4*)(sm + NSM_W);
        #pragma unroll
        for (int i = tid; i < 2048; i += 256) d[i] = __ldg(s + i);
    }
    load_convert_A<true, false>(h, norm, row0, M, sm + NSM_A);
    __syncthreads();

    int lane = tid & 31, w = tid >> 5;
    int rbase = row0 + w * 16 + (lane >> 2);
    int cp = 2 * (lane & 3);

    #pragma unroll
    for (int half = 0; half < 2; half++) {
        float acc[8][4];
        gemm_fp16_half(sm + NSM_A, sm + NSM_W, half, acc);
        #pragma unroll
        for (int n8 = 0; n8 < 8; n8++) {
            int c = half * 64 + n8 * 8 + cp;
            float2 bv = __ldg((const float2*)(bias + c));
            if (bias2) {
                float2 b2 = __ldg((const float2*)(bias2 + c));
                bv.x += b2.x; bv.y += b2.y;
            }
            #pragma unroll
            for (int rr = 0; rr < 2; rr++) {
                int r = rbase + rr * 8;
                if (r < M) {
                    float2 v = make_float2(acc[n8][rr * 2] + bv.x, acc[n8][rr * 2 + 1] + bv.y);
                    if (y == 0) {
                        *(float2*)(g_Ah + (size_t)r * DD + c) = v;
                    } else if (y == 3) {
                        *(__half2*)(g_Eh16 + (size_t)r * DD + c) = __floats2half2_rn(v.x, v.y);
                    } else {
                        // interleaved fp16 blocks: node*256 + 8*(c>>2) + (c&3), Bh at +4
                        size_t base = (size_t)r * (2 * DD) + 8 * (c >> 2) + (c & 3)
                                    + (y == 1 ? 4 : 0);
                        *(__half2*)(g_DB + base) = __floats2half2_rn(v.x, v.y);
                    }
                }
            }
        }
    }
}

// ---------------- edge kernel: tile per CTA; pipelined row-granular epilogue ----------------
__global__ __launch_bounds__(256, 2) void edge_mma_kernel(
        const float* __restrict__ e,
        const int* __restrict__ src, const int* __restrict__ dst,
        float* __restrict__ out_e, int E) {
    extern __shared__ unsigned char sm[];
    int tid = threadIdx.x;
    int tile = blockIdx.x;

    {   // Wc (index 2)
        const uint4* s = (const uint4*)(g_Wh + 2 * 32768);
        uint4* d = (uint4*)(sm + ESM_W);
        #pragma unroll
        for (int i = tid; i < 2048; i += 256) d[i] = __ldg(s + i);
    }
    // stage src/dst pairs for the tile
    if (tid < 128) {
        int er = tile * 128 + tid;
        int2 sd = (er < E) ? make_int2(__ldg(src + er), __ldg(dst + er))
                           : make_int2(0, 0);
        ((int2*)(sm + ESM_I))[tid] = sd;
    }
    load_convert_A<false, true>(e, nullptr, tile * 128, E, sm + ESM_A);
    __syncthreads();

    int lane = tid & 31, w = tid >> 5;
    float* Cf = (float*)(sm + ESM_C);
    const int2* sidx = (const int2*)(sm + ESM_I);

    // staging coords (fragment layout)
    int sr0 = w * 16 + (lane >> 2);
    int scp = 2 * (lane & 3);
    // epilogue coords (row-granular: 2 edges per warp instruction)
    int sub = lane >> 4;            // 0/1: which of the two edges
    int j   = lane & 15;            // 16 lanes cover 64 cols as float4

    #pragma unroll
    for (int half = 0; half < 2; half++) {
        float acc[8][4];
        gemm_fp16_half(sm + ESM_A, sm + ESM_W, half, acc);

        // stage this warp's 16 rows x 64 cols into warp-private C region
        __syncwarp();
        #pragma unroll
        for (int n8 = 0; n8 < 8; n8++) {
            int cl = n8 * 8 + scp;
            *(float2*)(Cf + cswz(sr0, cl))     = make_float2(acc[n8][0], acc[n8][1]);
            *(float2*)(Cf + cswz(sr0 + 8, cl)) = make_float2(acc[n8][2], acc[n8][3]);
        }
        __syncwarp();

        int jj = half * 16 + j;
        int cc = half * 64 + 4 * j;

        // software-pipelined epilogue: prefetch gathers one iteration ahead
        // one uint4 = {Dh[4], Bh[4]} fp16; one uint2 = Eh[4] fp16
        int2 sd = sidx[w * 16 + sub];
        uint4 pdb = __ldg((const uint4*)(g_DB + (size_t)sd.x * (2 * DD) + 8 * jj));
        uint2 peh = __ldg((const uint2*)(g_Eh16 + (size_t)sd.y * DD + cc));

        #pragma unroll
        for (int k = 0; k < 8; k++) {
            int lr = w * 16 + 2 * k + sub;
            int er = tile * 128 + lr;
            uint4 db = pdb;
            uint2 eh = peh;
            int dcur = sd.y;
            if (k < 7) {
                sd = sidx[lr + 2];
                pdb = __ldg((const uint4*)(g_DB + (size_t)sd.x * (2 * DD) + 8 * jj));
                peh = __ldg((const uint2*)(g_Eh16 + (size_t)sd.y * DD + cc));
            }
            if (er < E) {
                float4 cx = *(const float4*)(Cf + cswz(lr, 4 * j));
                float2 d01 = h2f(db.x), d23 = h2f(db.y);
                float2 b01 = h2f(db.z), b23 = h2f(db.w);
                float2 e01 = h2f(eh.x), e23 = h2f(eh.y);
                float4 x;
                x.x = cx.x + d01.x + e01.x;    // Dh includes bd + bc
                x.y = cx.y + d01.y + e01.y;
                x.z = cx.z + d23.x + e23.x;
                x.w = cx.w + d23.y + e23.y;
                __stcs((float4*)(out_e + (size_t)er * DD + cc), x);
                float4 sg;
                sg.x = __fdividef(1.f, 1.f + __expf(-x.x));
                sg.y = __fdividef(1.f, 1.f + __expf(-x.y));
                sg.z = __fdividef(1.f, 1.f + __expf(-x.z));
                sg.w = __fdividef(1.f, 1.f + __expf(-x.w));
                float4 nm4 = make_float4(sg.x * b01.x, sg.y * b01.y,
                                         sg.z * b23.x, sg.w * b23.y);
                float* ndp = g_nd + (size_t)dcur * (2 * DD) + 8 * jj;
                red_add_v4(ndp, nm4);
                red_add_v4(ndp + 4, sg);
            }
        }
        __syncwarp();   // C reuse across halves is warp-local
    }
}

// ---------------- finalize (deg>0 <=> den>0, sigmoids strictly positive) ----------------
__global__ void finalize_kernel(const float* __restrict__ h,
                                const float* __restrict__ norm,
                                float* __restrict__ out_h, int Nn) {
    int idx = blockIdx.x * blockDim.x + threadIdx.x;   // float4-block index
    int total = Nn * (DD / 4);
    if (idx >= total) return;
    int node = idx >> 5;
    int jj = idx & 31;
    float nm = __ldg(norm + node);
    const float* ndp = g_nd + (size_t)node * (2 * DD) + 8 * jj;
    float4 nu = *(const float4*)(ndp);
    float4 de = *(const float4*)(ndp + 4);
    float4 r;
    if (de.x > 0.f) {
        float4 a = ((const float4*)g_Ah)[idx];
        r.x = (a.x + nu.x / (de.x + 1e-6f)) * nm;
        r.y = (a.y + nu.y / (de.y + 1e-6f)) * nm;
        r.z = (a.z + nu.z / (de.z + 1e-6f)) * nm;
        r.w = (a.w + nu.w / (de.w + 1e-6f)) * nm;
    } else {
        float4 hh = *(const float4*)(h + (size_t)idx * 4);
        float sc = nm * nm;
        r = make_float4(hh.x * sc, hh.y * sc, hh.z * sc, hh.w * sc);
    }
    ((float4*)out_h)[idx] = r;
}

// ---------------- launch ----------------
extern "C" void kernel_launch(void* const* d_in, const int* in_sizes, int n_in,
                              void* d_out, int out_size) {
    const float* h    = (const float*)d_in[0];
    const float* e    = (const float*)d_in[1];
    const float* norm = (const float*)d_in[2];
    const int*   src  = (const int*)d_in[3];
    const int*   dst  = (const int*)d_in[4];
    const float* Wa = (const float*)d_in[5],  *ba = (const float*)d_in[6];
    const float* Wb = (const float*)d_in[7],  *bb = (const float*)d_in[8];
    const float* Wc = (const float*)d_in[9],  *bc = (const float*)d_in[10];
    const float* Wd = (const float*)d_in[11], *bd = (const float*)d_in[12];
    const float* We = (const float*)d_in[13], *be = (const float*)d_in[14];

    int Nn = in_sizes[0] / DD;   // 40000
    int Ee = in_sizes[3];        // 600000

    float* out_h = (float*)d_out;
    float* out_e = out_h + (size_t)Nn * DD;

    cudaFuncSetAttribute(node_mma_kernel, cudaFuncAttributeMaxDynamicSharedMemorySize, NSM_REQ);
    cudaFuncSetAttribute(edge_mma_kernel, cudaFuncAttributeMaxDynamicSharedMemorySize, ESM_REQ);

    // launch order: edge kernel is the 4th launch (ncu captures #4)
    prep_kernel<<<(5 * 16384 + 255) / 256, 256>>>(Wa, Wb, Wc, Wd, We);

    zero_kernel<<<(Nn * (2 * DD / 4) + 255) / 256, 256>>>(Nn);

    dim3 ngrid((Nn + 127) / 128, 4);
    node_mma_kernel<<<ngrid, 256, NSM_REQ>>>(h, norm, ba, bb, bd, be, bc, Nn);

    edge_mma_kernel<<<(Ee + 127) / 128, 256, ESM_REQ>>>(e, src, dst, out_e, Ee);

    finalize_kernel<<<(Nn * (DD / 4) + 255) / 256, 256>>>(h, norm, out_h, Nn);
}